// round 9
// baseline (speedup 1.0000x reference)
#include <cuda_runtime.h>
#include <cuda_fp16.h>
#include <cstdint>

#define NTOK 4096
#define DDIM 1024
#define EEXP 8
#define FDIM 4096

#define BM 128
#define BN 256
#define BK 64
#define NSTAGE 3

// smem per stage: A 128 rows x 144B (128B data + 16B pad); B 64 rows x 528B
#define AROWB 144
#define BROWB 528
#define OFF_A  0
#define OFF_B  18432
#define STAGE  52224
#define SMEM_TOTAL (NSTAGE * STAGE)   // 156672

// ---------------- scratch ---------------------------------------------------
__device__ int    d_bucket[EEXP * NTOK];
__device__ int    d_expCount[EEXP];
__device__ float  d_scale[NTOK];
__device__ float  d_psPartial[512 * EEXP];
__device__ __half d_x16[(size_t)NTOK * DDIM];
__device__ __half d_w1_16[(size_t)EEXP * DDIM * FDIM];  // [E][K][N]
__device__ __half d_w2_16[(size_t)EEXP * FDIM * DDIM];  // [E][K][N]
__device__ __half d_h16[(size_t)NTOK * FDIM];

// ---------------- helpers ---------------------------------------------------
__device__ __forceinline__ uint32_t smem_u32(const void* p) {
    uint32_t a;
    asm("{ .reg .u64 t; cvta.to.shared.u64 t, %1; cvt.u32.u64 %0, t; }"
        : "=r"(a) : "l"(p));
    return a;
}
__device__ __forceinline__ void cp16(uint32_t s, const void* g) {
    asm volatile("cp.async.cg.shared.global [%0], [%1], 16;" :: "r"(s), "l"(g));
}
__device__ __forceinline__ void cp_commit() {
    asm volatile("cp.async.commit_group;" ::: "memory");
}
__device__ __forceinline__ void cp_wait_deep() {
    asm volatile("cp.async.wait_group %0;" :: "n"(NSTAGE - 2) : "memory");
}
__device__ __forceinline__ void ldm4(uint32_t* r, uint32_t a) {
    asm volatile("ldmatrix.sync.aligned.m8n8.x4.shared.b16 {%0,%1,%2,%3}, [%4];"
                 : "=r"(r[0]), "=r"(r[1]), "=r"(r[2]), "=r"(r[3]) : "r"(a));
}
__device__ __forceinline__ void ldm4t(uint32_t* r, uint32_t a) {
    asm volatile("ldmatrix.sync.aligned.m8n8.x4.trans.shared.b16 {%0,%1,%2,%3}, [%4];"
                 : "=r"(r[0]), "=r"(r[1]), "=r"(r[2]), "=r"(r[3]) : "r"(a));
}
__device__ __forceinline__ void mma16816(float* c, const uint32_t* a, const uint32_t* b) {
    asm volatile("mma.sync.aligned.m16n8k16.row.col.f32.f16.f16.f32 "
                 "{%0,%1,%2,%3}, {%4,%5,%6,%7}, {%8,%9}, {%0,%1,%2,%3};"
                 : "+f"(c[0]), "+f"(c[1]), "+f"(c[2]), "+f"(c[3])
                 : "r"(a[0]), "r"(a[1]), "r"(a[2]), "r"(a[3]),
                   "r"(b[0]), "r"(b[1]));
}
__device__ __forceinline__ uint32_t pack_h2(float a, float b) {
    __half2 h = __floats2half2_rn(a, b);
    return *reinterpret_cast<uint32_t*>(&h);
}

// ---------------- init ------------------------------------------------------
__global__ void init_kernel() {
    if (threadIdx.x < EEXP) d_expCount[threadIdx.x] = 0;
}

// ---------------- routing (1 warp / token, fp64 acc) + x fp16 conversion ----
__global__ void route_kernel(const float* __restrict__ x,
                             const float* __restrict__ wsw,
                             const float* __restrict__ bsw,
                             __half* __restrict__ x16) {
    // fused: convert this block's share of x to fp16 (8 float4 per thread)
    {
        int base = (blockIdx.x * blockDim.x + threadIdx.x) * 8;
#pragma unroll
        for (int i = 0; i < 8; i++) {
            float4 v = ((const float4*)x)[base + i];
            ((uint2*)x16)[base + i] =
                make_uint2(pack_h2(v.x, v.y), pack_h2(v.z, v.w));
        }
    }

    int warp = threadIdx.x >> 5;
    int lane = threadIdx.x & 31;
    int token = blockIdx.x * 8 + warp;

    const float* xr = x + (size_t)token * DDIM;
    double acc[8];
#pragma unroll
    for (int e = 0; e < 8; e++) acc[e] = 0.0;

    for (int i = lane; i < DDIM; i += 32) {
        float xv = xr[i];
        float4 wa = *(const float4*)(wsw + (size_t)i * 8);
        float4 wb = *(const float4*)(wsw + (size_t)i * 8 + 4);
        acc[0] += (double)xv * wa.x;
        acc[1] += (double)xv * wa.y;
        acc[2] += (double)xv * wa.z;
        acc[3] += (double)xv * wa.w;
        acc[4] += (double)xv * wb.x;
        acc[5] += (double)xv * wb.y;
        acc[6] += (double)xv * wb.z;
        acc[7] += (double)xv * wb.w;
    }
#pragma unroll
    for (int e = 0; e < 8; e++) {
#pragma unroll
        for (int off = 16; off > 0; off >>= 1)
            acc[e] += __shfl_down_sync(0xffffffffu, acc[e], off);
    }

    __shared__ float probs[8][8];
    if (lane == 0) {
        float l[8];
#pragma unroll
        for (int e = 0; e < 8; e++) l[e] = (float)acc[e] + bsw[e];
        int am = 0;
        float mx = l[0];
#pragma unroll
        for (int e = 1; e < 8; e++)
            if (l[e] > mx) { mx = l[e]; am = e; }
        float p[8], sum = 0.0f;
#pragma unroll
        for (int e = 0; e < 8; e++) { p[e] = expf(l[e] - mx); sum += p[e]; }
        float inv = 1.0f / sum;
#pragma unroll
        for (int e = 0; e < 8; e++) probs[warp][e] = p[e] * inv;

        d_scale[token] = inv;
        int pos = atomicAdd(&d_expCount[am], 1);
        d_bucket[am * NTOK + pos] = token;
    }
    __syncthreads();
    if (threadIdx.x < 8) {
        float s = 0.0f;
#pragma unroll
        for (int w = 0; w < 8; w++) s += probs[w][threadIdx.x];
        d_psPartial[blockIdx.x * 8 + threadIdx.x] = s;
    }
}

// ---------------- prep: fp32 -> fp16 conversion (w1 only) -------------------
__global__ void convf_kernel(const float* __restrict__ src,
                             __half* __restrict__ dst) {
    int i = blockIdx.x * blockDim.x + threadIdx.x;   // one float4 each
    float4 v = ((const float4*)src)[i];
    ((uint2*)dst)[i] = make_uint2(pack_h2(v.x, v.y), pack_h2(v.z, v.w));
}

// ---------------- grouped GEMM: all fp16, single-pass, BK=64 ----------------
// MODE 1: h = relu(scale * x @ w1 + b1) -> fp16 store; ALSO converts its
//         share of w2 fp32->fp16 (rides GEMM1's idle DRAM pipe).
// MODE 2: out = h @ w2 + b2 -> fp32 scatter
template <int MODE>
__global__ __launch_bounds__(256, 1)
void moe_gemm_kernel(const __half* __restrict__ A16,
                     const __half* __restrict__ W16,
                     const float* __restrict__ bias,
                     float* __restrict__ out,
                     __half* __restrict__ oF,
                     const float* __restrict__ cvSrc,
                     __half* __restrict__ cvDst,
                     int Ntot, int Ktot) {
    int e = blockIdx.z;
    int cnt = d_expCount[e];
    int mBase = blockIdx.y * BM;
    int nBase = blockIdx.x * BN;
    int tid = threadIdx.x;

    // ---- fused conversion share (MODE 1): run BEFORE any early exit ----
    if (MODE == 1) {
        int cta = (blockIdx.z * gridDim.y + blockIdx.y) * gridDim.x + blockIdx.x;
        // total w2 elems = 8*4096*1024 = 33554432 = 8388608 float4
        // 4096 CTAs -> 2048 float4/CTA -> 8 per thread
        int base = cta * 2048 + tid * 8;
#pragma unroll
        for (int i = 0; i < 8; i++) {
            float4 v = ((const float4*)cvSrc)[base + i];
            ((uint2*)cvDst)[base + i] =
                make_uint2(pack_h2(v.x, v.y), pack_h2(v.z, v.w));
        }
    }
    if (mBase >= cnt) return;

    extern __shared__ char smem[];
    uint32_t sb = smem_u32(smem);
    int wid = tid >> 5;
    int lane = tid & 31;

    // ---- loader assignment ----
    // A: 128 rows x 128B/stage; thread -> (row tid>>1, 64B half tid&1)
    int r2 = tid >> 1;
    int hb = tid & 1;
    bool aValid = (mBase + r2) < cnt;
    int aTok = aValid ? d_bucket[e * NTOK + mBase + r2] : d_bucket[e * NTOK];
    const __half* aP = A16 + (size_t)aTok * Ktot + hb * 32;
    uint32_t sAoff = r2 * AROWB + hb * 64;

    // B: 64 k-rows x 512B/stage; thread -> (row tid>>2, 128B seg tid&3)
    int rowB = tid >> 2;
    int segB = tid & 3;
    const __half* bP = W16 + (size_t)e * (size_t)Ktot * Ntot +
                       (size_t)rowB * Ntot + nBase + segB * 64;
    uint32_t sBoff = rowB * BROWB + segB * 128;

    auto load_stage = [&](int st, int k0) {
        uint32_t dst = sb + st * STAGE;
#pragma unroll
        for (int q = 0; q < 4; q++)
            cp16(dst + OFF_A + sAoff + q * 16, aP + k0 + q * 8);
        size_t kk = (size_t)k0 * Ntot;
#pragma unroll
        for (int q = 0; q < 8; q++)
            cp16(dst + OFF_B + sBoff + q * 16, bP + kk + q * 8);
    };

    // ---- compute assignment: 2 warpM x 4 warpN, warp tile 64x64 ----
    int warpM = wid >> 2;
    int warpN = wid & 3;
    int m0 = warpM * 64;
    int n0 = warpN * 64;

    float acc[32][4];
#pragma unroll
    for (int i = 0; i < 32; i++)
#pragma unroll
        for (int j = 0; j < 4; j++) acc[i][j] = 0.0f;

    int aRowL = m0 + (lane & 15);
    int aColB = (lane >> 4) * 16;
    int bKoff = (lane & 7) + ((lane >> 3) & 1) * 8;
    int bNoff = ((lane >> 4) & 1) * 8;

    auto compute_stage = [&](int st) {
        uint32_t base = sb + st * STAGE;
#pragma unroll
        for (int s = 0; s < 4; s++) {     // four k16 steps per BK=64 stage
            uint32_t a[4][4];
            uint32_t aAddr = base + OFF_A + aRowL * AROWB + aColB + s * 32;
#pragma unroll
            for (int mi = 0; mi < 4; mi++)
                ldm4(a[mi], aAddr + mi * 16 * AROWB);

            uint32_t b[4][4];
#pragma unroll
            for (int l = 0; l < 4; l++) {
                uint32_t bAddr = base + OFF_B + (s * 16 + bKoff) * BROWB +
                                 (n0 + l * 16 + bNoff) * 2;
                ldm4t(b[l], bAddr);
            }
#pragma unroll
            for (int mi = 0; mi < 4; mi++)
#pragma unroll
                for (int l = 0; l < 4; l++) {
                    mma16816(acc[mi * 8 + 2 * l],     a[mi], b[l]);
                    mma16816(acc[mi * 8 + 2 * l + 1], a[mi], b[l] + 2);
                }
        }
    };

    const int T = Ktot / BK;

    // prologue: fill NSTAGE-1 stages
#pragma unroll
    for (int i = 0; i < NSTAGE - 1; i++) {
        load_stage(i, i * BK);
        cp_commit();
    }

    for (int t = 0; t < T; t++) {
        cp_wait_deep();            // stage t resident
        __syncthreads();           // WAR protection on reused stage
        if (t + NSTAGE - 1 < T)
            load_stage((t + NSTAGE - 1) % NSTAGE, (t + NSTAGE - 1) * BK);
        cp_commit();               // always commit (empty near tail)
        compute_stage(t % NSTAGE);
    }

    // ---- epilogue ----
#pragma unroll
    for (int mi = 0; mi < 4; mi++) {
#pragma unroll
        for (int half = 0; half < 2; half++) {
            int r = m0 + mi * 16 + half * 8 + (lane >> 2);
            int m = mBase + r;
            if (m >= cnt) continue;
            int token = d_bucket[e * NTOK + m];
            float sc = (MODE == 1) ? d_scale[token] : 1.0f;
#pragma unroll
            for (int nj = 0; nj < 8; nj++) {
                int col = nBase + n0 + nj * 8 + (lane & 3) * 2;
                float2 bv = *(const float2*)(bias + (size_t)e * Ntot + col);
                float v0 = acc[mi * 8 + nj][half * 2];
                float v1 = acc[mi * 8 + nj][half * 2 + 1];
                if (MODE == 1) {
                    v0 = fmaxf(v0 * sc + bv.x, 0.f);
                    v1 = fmaxf(v1 * sc + bv.y, 0.f);
                    *(uint32_t*)(oF + (size_t)token * Ntot + col) = pack_h2(v0, v1);
                } else {
                    float2 o;
                    o.x = v0 + bv.x;
                    o.y = v1 + bv.y;
                    *(float2*)(out + (size_t)token * Ntot + col) = o;
                }
            }
        }
    }
}

// ---------------- finalize ---------------------------------------------------
__global__ void finalize_kernel(float* __restrict__ out, int out_size) {
    int e = threadIdx.x;
    if (e >= 8) return;
    float s = 0.0f;
    for (int b = 0; b < 512; b++) s += d_psPartial[b * 8 + e];
    const int base = NTOK * DDIM;
    if (base + e < out_size)     out[base + e]     = (float)d_expCount[e];
    if (base + 8 + e < out_size) out[base + 8 + e] = s;
    if (e == 0 && base + 16 < out_size) out[base + 16] = 0.0f;
}

// ---------------- launch -----------------------------------------------------
extern "C" void kernel_launch(void* const* d_in, const int* in_sizes, int n_in,
                              void* d_out, int out_size) {
    const float* x   = (const float*)d_in[0];
    const float* wsw = (const float*)d_in[1];
    const float* bsw = (const float*)d_in[2];
    const float* w1  = (const float*)d_in[3];
    const float* b1  = (const float*)d_in[4];
    const float* w2  = (const float*)d_in[5];
    const float* b2  = (const float*)d_in[6];
    float* out = (float*)d_out;

    cudaFuncSetAttribute(moe_gemm_kernel<1>,
                         cudaFuncAttributeMaxDynamicSharedMemorySize, SMEM_TOTAL);
    cudaFuncSetAttribute(moe_gemm_kernel<2>,
                         cudaFuncAttributeMaxDynamicSharedMemorySize, SMEM_TOTAL);

    __half *x16, *w116, *w216, *h16;
    cudaGetSymbolAddress((void**)&x16, d_x16);
    cudaGetSymbolAddress((void**)&w116, d_w1_16);
    cudaGetSymbolAddress((void**)&w216, d_w2_16);
    cudaGetSymbolAddress((void**)&h16, d_h16);

    init_kernel<<<1, 32>>>();
    route_kernel<<<512, 256>>>(x, wsw, bsw, x16);       // also converts x
    convf_kernel<<<EEXP * DDIM * FDIM / 4 / 256, 256>>>(w1, w116);

    // GEMM1 also converts w2 (fused, rides idle DRAM pipe)
    moe_gemm_kernel<1><<<dim3(FDIM / BN, NTOK / BM, EEXP), 256, SMEM_TOTAL>>>(
        x16, w116, b1, nullptr, h16, w2, w216, FDIM, DDIM);
    moe_gemm_kernel<2><<<dim3(DDIM / BN, NTOK / BM, EEXP), 256, SMEM_TOTAL>>>(
        h16, w216, b2, out, nullptr, nullptr, nullptr, DDIM, FDIM);

    finalize_kernel<<<1, 8>>>(out, out_size);
}

// round 10
// speedup vs baseline: 1.0312x; 1.0312x over previous
#include <cuda_runtime.h>
#include <cuda_fp16.h>
#include <cstdint>

#define NTOK 4096
#define DDIM 1024
#define EEXP 8
#define FDIM 4096

#define BM 128
#define BN 256
#define BK 64
#define NSTAGE 3

// smem per stage: A 128 rows x 144B (128B data + 16B pad); B 64 rows x 528B
#define AROWB 144
#define BROWB 528
#define OFF_A  0
#define OFF_B  18432
#define STAGE  52224
#define SMEM_TOTAL (NSTAGE * STAGE)   // 156672

// ---------------- scratch ---------------------------------------------------
__device__ int    d_bucket[EEXP * NTOK];
__device__ int    d_expCount[EEXP];
__device__ float  d_scale[NTOK];
__device__ float  d_psPartial[512 * EEXP];
__device__ __half d_x16[(size_t)NTOK * DDIM];
__device__ __half d_w1_16[(size_t)EEXP * DDIM * FDIM];  // [E][K][N]
__device__ __half d_w2_16[(size_t)EEXP * FDIM * DDIM];  // [E][K][N]
__device__ __half d_h16[(size_t)NTOK * FDIM];

// ---------------- helpers ---------------------------------------------------
__device__ __forceinline__ uint32_t smem_u32(const void* p) {
    uint32_t a;
    asm("{ .reg .u64 t; cvta.to.shared.u64 t, %1; cvt.u32.u64 %0, t; }"
        : "=r"(a) : "l"(p));
    return a;
}
__device__ __forceinline__ void cp16(uint32_t s, const void* g) {
    asm volatile("cp.async.cg.shared.global [%0], [%1], 16;" :: "r"(s), "l"(g));
}
__device__ __forceinline__ void cp_commit() {
    asm volatile("cp.async.commit_group;" ::: "memory");
}
__device__ __forceinline__ void cp_wait_deep() {
    asm volatile("cp.async.wait_group %0;" :: "n"(NSTAGE - 2) : "memory");
}
__device__ __forceinline__ void ldm4(uint32_t* r, uint32_t a) {
    asm volatile("ldmatrix.sync.aligned.m8n8.x4.shared.b16 {%0,%1,%2,%3}, [%4];"
                 : "=r"(r[0]), "=r"(r[1]), "=r"(r[2]), "=r"(r[3]) : "r"(a));
}
__device__ __forceinline__ void ldm4t(uint32_t* r, uint32_t a) {
    asm volatile("ldmatrix.sync.aligned.m8n8.x4.trans.shared.b16 {%0,%1,%2,%3}, [%4];"
                 : "=r"(r[0]), "=r"(r[1]), "=r"(r[2]), "=r"(r[3]) : "r"(a));
}
__device__ __forceinline__ void mma16816(float* c, const uint32_t* a, const uint32_t* b) {
    asm volatile("mma.sync.aligned.m16n8k16.row.col.f32.f16.f16.f32 "
                 "{%0,%1,%2,%3}, {%4,%5,%6,%7}, {%8,%9}, {%0,%1,%2,%3};"
                 : "+f"(c[0]), "+f"(c[1]), "+f"(c[2]), "+f"(c[3])
                 : "r"(a[0]), "r"(a[1]), "r"(a[2]), "r"(a[3]),
                   "r"(b[0]), "r"(b[1]));
}
__device__ __forceinline__ uint32_t pack_h2(float a, float b) {
    __half2 h = __floats2half2_rn(a, b);
    return *reinterpret_cast<uint32_t*>(&h);
}

// ---------------- init ------------------------------------------------------
__global__ void init_kernel() {
    if (threadIdx.x < EEXP) d_expCount[threadIdx.x] = 0;
}

// ---------------- routing (1 warp / token, fp64 acc) + x fp16 conversion ----
__global__ void route_kernel(const float* __restrict__ x,
                             const float* __restrict__ wsw,
                             const float* __restrict__ bsw,
                             __half* __restrict__ x16) {
    // fused: convert this block's share of x to fp16 (8 float4 per thread)
    {
        int base = (blockIdx.x * blockDim.x + threadIdx.x) * 8;
#pragma unroll
        for (int i = 0; i < 8; i++) {
            float4 v = ((const float4*)x)[base + i];
            ((uint2*)x16)[base + i] =
                make_uint2(pack_h2(v.x, v.y), pack_h2(v.z, v.w));
        }
    }

    int warp = threadIdx.x >> 5;
    int lane = threadIdx.x & 31;
    int token = blockIdx.x * 8 + warp;

    const float* xr = x + (size_t)token * DDIM;
    double acc[8];
#pragma unroll
    for (int e = 0; e < 8; e++) acc[e] = 0.0;

    for (int i = lane; i < DDIM; i += 32) {
        float xv = xr[i];
        float4 wa = *(const float4*)(wsw + (size_t)i * 8);
        float4 wb = *(const float4*)(wsw + (size_t)i * 8 + 4);
        acc[0] += (double)xv * wa.x;
        acc[1] += (double)xv * wa.y;
        acc[2] += (double)xv * wa.z;
        acc[3] += (double)xv * wa.w;
        acc[4] += (double)xv * wb.x;
        acc[5] += (double)xv * wb.y;
        acc[6] += (double)xv * wb.z;
        acc[7] += (double)xv * wb.w;
    }
#pragma unroll
    for (int e = 0; e < 8; e++) {
#pragma unroll
        for (int off = 16; off > 0; off >>= 1)
            acc[e] += __shfl_down_sync(0xffffffffu, acc[e], off);
    }

    __shared__ float probs[8][8];
    if (lane == 0) {
        float l[8];
#pragma unroll
        for (int e = 0; e < 8; e++) l[e] = (float)acc[e] + bsw[e];
        int am = 0;
        float mx = l[0];
#pragma unroll
        for (int e = 1; e < 8; e++)
            if (l[e] > mx) { mx = l[e]; am = e; }
        float p[8], sum = 0.0f;
#pragma unroll
        for (int e = 0; e < 8; e++) { p[e] = expf(l[e] - mx); sum += p[e]; }
        float inv = 1.0f / sum;
#pragma unroll
        for (int e = 0; e < 8; e++) probs[warp][e] = p[e] * inv;

        d_scale[token] = inv;
        int pos = atomicAdd(&d_expCount[am], 1);
        d_bucket[am * NTOK + pos] = token;
    }
    __syncthreads();
    if (threadIdx.x < 8) {
        float s = 0.0f;
#pragma unroll
        for (int w = 0; w < 8; w++) s += probs[w][threadIdx.x];
        d_psPartial[blockIdx.x * 8 + threadIdx.x] = s;
    }
}

// ---------------- prep: fp32 -> fp16 conversion (weights) -------------------
__global__ void convf_kernel(const float* __restrict__ src,
                             __half* __restrict__ dst) {
    int i = blockIdx.x * blockDim.x + threadIdx.x;   // one float4 each
    float4 v = ((const float4*)src)[i];
    ((uint2*)dst)[i] = make_uint2(pack_h2(v.x, v.y), pack_h2(v.z, v.w));
}

// ---------------- grouped GEMM: fp16 single-pass, BK=64, frag-pipelined -----
// MODE 1: h = relu(scale * x @ w1 + b1) -> fp16 store
// MODE 2: out = h @ w2 + b2 -> fp32 scatter
template <int MODE>
__global__ __launch_bounds__(256, 1)
void moe_gemm_kernel(const __half* __restrict__ A16,
                     const __half* __restrict__ W16,
                     const float* __restrict__ bias,
                     float* __restrict__ out,
                     __half* __restrict__ oF,
                     int Ntot, int Ktot) {
    int e = blockIdx.z;
    int cnt = d_expCount[e];
    int mBase = blockIdx.y * BM;
    if (mBase >= cnt) return;
    int nBase = blockIdx.x * BN;

    extern __shared__ char smem[];
    uint32_t sb = smem_u32(smem);
    int tid = threadIdx.x;
    int wid = tid >> 5;
    int lane = tid & 31;

    // ---- loader assignment ----
    // A: 128 rows x 128B/stage; thread -> (row tid>>1, 64B half tid&1)
    int r2 = tid >> 1;
    int hb = tid & 1;
    bool aValid = (mBase + r2) < cnt;
    int aTok = aValid ? d_bucket[e * NTOK + mBase + r2] : d_bucket[e * NTOK];
    const __half* aP = A16 + (size_t)aTok * Ktot + hb * 32;
    uint32_t sAoff = r2 * AROWB + hb * 64;

    // B: 64 k-rows x 512B/stage; thread -> (row tid>>2, 128B seg tid&3)
    int rowB = tid >> 2;
    int segB = tid & 3;
    const __half* bP = W16 + (size_t)e * (size_t)Ktot * Ntot +
                       (size_t)rowB * Ntot + nBase + segB * 64;
    uint32_t sBoff = rowB * BROWB + segB * 128;

    auto load_stage = [&](int st, int k0) {
        uint32_t dst = sb + st * STAGE;
#pragma unroll
        for (int q = 0; q < 4; q++)
            cp16(dst + OFF_A + sAoff + q * 16, aP + k0 + q * 8);
        size_t kk = (size_t)k0 * Ntot;
#pragma unroll
        for (int q = 0; q < 8; q++)
            cp16(dst + OFF_B + sBoff + q * 16, bP + kk + q * 8);
    };

    // ---- compute assignment: 2 warpM x 4 warpN, warp tile 64x64 ----
    int warpM = wid >> 2;
    int warpN = wid & 3;
    int m0 = warpM * 64;
    int n0 = warpN * 64;

    float acc[32][4];
#pragma unroll
    for (int i = 0; i < 32; i++)
#pragma unroll
        for (int j = 0; j < 4; j++) acc[i][j] = 0.0f;

    int aRowL = m0 + (lane & 15);
    int aColB = (lane >> 4) * 16;
    int bKoff = (lane & 7) + ((lane >> 3) & 1) * 8;
    int bNoff = ((lane >> 4) & 1) * 8;

    // double-buffered fragments: buffer s&1 holds k-step s
    uint32_t af[2][4][4], bf[2][4][4];

    auto ldfrag = [&](int st, int s, int buf) {
        uint32_t base = sb + st * STAGE;
        uint32_t aAddr = base + OFF_A + aRowL * AROWB + aColB + s * 32;
#pragma unroll
        for (int mi = 0; mi < 4; mi++)
            ldm4(af[buf][mi], aAddr + mi * 16 * AROWB);
#pragma unroll
        for (int l = 0; l < 4; l++) {
            uint32_t bAddr = base + OFF_B + (s * 16 + bKoff) * BROWB +
                             (n0 + l * 16 + bNoff) * 2;
            ldm4t(bf[buf][l], bAddr);
        }
    };

    auto domma = [&](int buf) {
#pragma unroll
        for (int mi = 0; mi < 4; mi++)
#pragma unroll
            for (int l = 0; l < 4; l++) {
                mma16816(acc[mi * 8 + 2 * l],     af[buf][mi], bf[buf][l]);
                mma16816(acc[mi * 8 + 2 * l + 1], af[buf][mi], bf[buf][l] + 2);
            }
    };

    const int T = Ktot / BK;

    // prologue: fill NSTAGE-1 stages
#pragma unroll
    for (int i = 0; i < NSTAGE - 1; i++) {
        load_stage(i, i * BK);
        cp_commit();
    }

    for (int t = 0; t < T; t++) {
        cp_wait_deep();            // stage t resident
        __syncthreads();           // WAR protection on reused stage
        if (t + NSTAGE - 1 < T)
            load_stage((t + NSTAGE - 1) % NSTAGE, (t + NSTAGE - 1) * BK);
        cp_commit();               // always commit (empty near tail)

        int st = t % NSTAGE;
        ldfrag(st, 0, 0);          // exposed once per stage
#pragma unroll
        for (int s = 0; s < 4; s++) {
            if (s + 1 < 4) ldfrag(st, s + 1, (s + 1) & 1);  // overlaps MMAs
            domma(s & 1);
        }
    }

    // ---- epilogue ----
#pragma unroll
    for (int mi = 0; mi < 4; mi++) {
#pragma unroll
        for (int half = 0; half < 2; half++) {
            int r = m0 + mi * 16 + half * 8 + (lane >> 2);
            int m = mBase + r;
            if (m >= cnt) continue;
            int token = d_bucket[e * NTOK + m];
            float sc = (MODE == 1) ? d_scale[token] : 1.0f;
#pragma unroll
            for (int nj = 0; nj < 8; nj++) {
                int col = nBase + n0 + nj * 8 + (lane & 3) * 2;
                float2 bv = *(const float2*)(bias + (size_t)e * Ntot + col);
                float v0 = acc[mi * 8 + nj][half * 2];
                float v1 = acc[mi * 8 + nj][half * 2 + 1];
                if (MODE == 1) {
                    v0 = fmaxf(v0 * sc + bv.x, 0.f);
                    v1 = fmaxf(v1 * sc + bv.y, 0.f);
                    *(uint32_t*)(oF + (size_t)token * Ntot + col) = pack_h2(v0, v1);
                } else {
                    float2 o;
                    o.x = v0 + bv.x;
                    o.y = v1 + bv.y;
                    *(float2*)(out + (size_t)token * Ntot + col) = o;
                }
            }
        }
    }
}

// ---------------- finalize ---------------------------------------------------
__global__ void finalize_kernel(float* __restrict__ out, int out_size) {
    int e = threadIdx.x;
    if (e >= 8) return;
    float s = 0.0f;
    for (int b = 0; b < 512; b++) s += d_psPartial[b * 8 + e];
    const int base = NTOK * DDIM;
    if (base + e < out_size)     out[base + e]     = (float)d_expCount[e];
    if (base + 8 + e < out_size) out[base + 8 + e] = s;
    if (e == 0 && base + 16 < out_size) out[base + 16] = 0.0f;
}

// ---------------- launch -----------------------------------------------------
extern "C" void kernel_launch(void* const* d_in, const int* in_sizes, int n_in,
                              void* d_out, int out_size) {
    const float* x   = (const float*)d_in[0];
    const float* wsw = (const float*)d_in[1];
    const float* bsw = (const float*)d_in[2];
    const float* w1  = (const float*)d_in[3];
    const float* b1  = (const float*)d_in[4];
    const float* w2  = (const float*)d_in[5];
    const float* b2  = (const float*)d_in[6];
    float* out = (float*)d_out;

    cudaFuncSetAttribute(moe_gemm_kernel<1>,
                         cudaFuncAttributeMaxDynamicSharedMemorySize, SMEM_TOTAL);
    cudaFuncSetAttribute(moe_gemm_kernel<2>,
                         cudaFuncAttributeMaxDynamicSharedMemorySize, SMEM_TOTAL);

    __half *x16, *w116, *w216, *h16;
    cudaGetSymbolAddress((void**)&x16, d_x16);
    cudaGetSymbolAddress((void**)&w116, d_w1_16);
    cudaGetSymbolAddress((void**)&w216, d_w2_16);
    cudaGetSymbolAddress((void**)&h16, d_h16);

    init_kernel<<<1, 32>>>();
    route_kernel<<<512, 256>>>(x, wsw, bsw, x16);       // also converts x
    convf_kernel<<<EEXP * DDIM * FDIM / 4 / 256, 256>>>(w1, w116);
    convf_kernel<<<EEXP * FDIM * DDIM / 4 / 256, 256>>>(w2, w216);

    moe_gemm_kernel<1><<<dim3(FDIM / BN, NTOK / BM, EEXP), 256, SMEM_TOTAL>>>(
        x16, w116, b1, nullptr, h16, FDIM, DDIM);
    moe_gemm_kernel<2><<<dim3(DDIM / BN, NTOK / BM, EEXP), 256, SMEM_TOTAL>>>(
        h16, w216, b2, out, nullptr, DDIM, FDIM);

    finalize_kernel<<<1, 8>>>(out, out_size);
}

// round 11
// speedup vs baseline: 1.1807x; 1.1450x over previous
#include <cuda_runtime.h>
#include <cuda_fp16.h>
#include <cstdint>

#define NTOK 4096
#define DDIM 1024
#define EEXP 8
#define FDIM 4096

#define BM 128
#define BN 256
#define BK 32
#define NSTAGE 6

// smem per stage: A 128 rows x 80B (64B data + 16B pad); B 32 rows x 528B
#define AROWB 80
#define BROWB 528
#define OFF_A  0
#define OFF_B  10240
#define STAGE  27136
#define SMEM_TOTAL (NSTAGE * STAGE)   // 162816

// ---------------- scratch ---------------------------------------------------
__device__ int    d_bucket[EEXP * NTOK];
__device__ int    d_expCount[EEXP];
__device__ float  d_scale[NTOK];
__device__ float  d_psPartial[512 * EEXP];
__device__ __half d_x16[(size_t)NTOK * DDIM];
__device__ __half d_w1_16[(size_t)EEXP * DDIM * FDIM];  // [E][K][N]
__device__ __half d_w2_16[(size_t)EEXP * FDIM * DDIM];  // [E][K][N]
__device__ __half d_h16[(size_t)NTOK * FDIM];

// ---------------- helpers ---------------------------------------------------
__device__ __forceinline__ uint32_t smem_u32(const void* p) {
    uint32_t a;
    asm("{ .reg .u64 t; cvta.to.shared.u64 t, %1; cvt.u32.u64 %0, t; }"
        : "=r"(a) : "l"(p));
    return a;
}
__device__ __forceinline__ void cp16(uint32_t s, const void* g) {
    asm volatile("cp.async.cg.shared.global [%0], [%1], 16;" :: "r"(s), "l"(g));
}
__device__ __forceinline__ void cp_commit() {
    asm volatile("cp.async.commit_group;" ::: "memory");
}
__device__ __forceinline__ void cp_wait_deep() {
    asm volatile("cp.async.wait_group %0;" :: "n"(NSTAGE - 2) : "memory");
}
__device__ __forceinline__ void ldm4(uint32_t* r, uint32_t a) {
    asm volatile("ldmatrix.sync.aligned.m8n8.x4.shared.b16 {%0,%1,%2,%3}, [%4];"
                 : "=r"(r[0]), "=r"(r[1]), "=r"(r[2]), "=r"(r[3]) : "r"(a));
}
__device__ __forceinline__ void ldm4t(uint32_t* r, uint32_t a) {
    asm volatile("ldmatrix.sync.aligned.m8n8.x4.trans.shared.b16 {%0,%1,%2,%3}, [%4];"
                 : "=r"(r[0]), "=r"(r[1]), "=r"(r[2]), "=r"(r[3]) : "r"(a));
}
__device__ __forceinline__ void mma16816(float* c, const uint32_t* a, const uint32_t* b) {
    asm volatile("mma.sync.aligned.m16n8k16.row.col.f32.f16.f16.f32 "
                 "{%0,%1,%2,%3}, {%4,%5,%6,%7}, {%8,%9}, {%0,%1,%2,%3};"
                 : "+f"(c[0]), "+f"(c[1]), "+f"(c[2]), "+f"(c[3])
                 : "r"(a[0]), "r"(a[1]), "r"(a[2]), "r"(a[3]),
                   "r"(b[0]), "r"(b[1]));
}
__device__ __forceinline__ uint32_t pack_h2(float a, float b) {
    __half2 h = __floats2half2_rn(a, b);
    return *reinterpret_cast<uint32_t*>(&h);
}

// ---------------- init ------------------------------------------------------
__global__ void init_kernel() {
    if (threadIdx.x < EEXP) d_expCount[threadIdx.x] = 0;
}

// ---------------- routing (1 warp / token, fp64 acc) + x fp16 conversion ----
__global__ void route_kernel(const float* __restrict__ x,
                             const float* __restrict__ wsw,
                             const float* __restrict__ bsw,
                             __half* __restrict__ x16) {
    // fused: convert this block's share of x to fp16 (8 float4 per thread)
    {
        int base = (blockIdx.x * blockDim.x + threadIdx.x) * 8;
#pragma unroll
        for (int i = 0; i < 8; i++) {
            float4 v = ((const float4*)x)[base + i];
            ((uint2*)x16)[base + i] =
                make_uint2(pack_h2(v.x, v.y), pack_h2(v.z, v.w));
        }
    }

    int warp = threadIdx.x >> 5;
    int lane = threadIdx.x & 31;
    int token = blockIdx.x * 8 + warp;

    const float* xr = x + (size_t)token * DDIM;
    double acc[8];
#pragma unroll
    for (int e = 0; e < 8; e++) acc[e] = 0.0;

    for (int i = lane; i < DDIM; i += 32) {
        float xv = xr[i];
        float4 wa = *(const float4*)(wsw + (size_t)i * 8);
        float4 wb = *(const float4*)(wsw + (size_t)i * 8 + 4);
        acc[0] += (double)xv * wa.x;
        acc[1] += (double)xv * wa.y;
        acc[2] += (double)xv * wa.z;
        acc[3] += (double)xv * wa.w;
        acc[4] += (double)xv * wb.x;
        acc[5] += (double)xv * wb.y;
        acc[6] += (double)xv * wb.z;
        acc[7] += (double)xv * wb.w;
    }
#pragma unroll
    for (int e = 0; e < 8; e++) {
#pragma unroll
        for (int off = 16; off > 0; off >>= 1)
            acc[e] += __shfl_down_sync(0xffffffffu, acc[e], off);
    }

    __shared__ float probs[8][8];
    if (lane == 0) {
        float l[8];
#pragma unroll
        for (int e = 0; e < 8; e++) l[e] = (float)acc[e] + bsw[e];
        int am = 0;
        float mx = l[0];
#pragma unroll
        for (int e = 1; e < 8; e++)
            if (l[e] > mx) { mx = l[e]; am = e; }
        float p[8], sum = 0.0f;
#pragma unroll
        for (int e = 0; e < 8; e++) { p[e] = expf(l[e] - mx); sum += p[e]; }
        float inv = 1.0f / sum;
#pragma unroll
        for (int e = 0; e < 8; e++) probs[warp][e] = p[e] * inv;

        d_scale[token] = inv;
        int pos = atomicAdd(&d_expCount[am], 1);
        d_bucket[am * NTOK + pos] = token;
    }
    __syncthreads();
    if (threadIdx.x < 8) {
        float s = 0.0f;
#pragma unroll
        for (int w = 0; w < 8; w++) s += probs[w][threadIdx.x];
        d_psPartial[blockIdx.x * 8 + threadIdx.x] = s;
    }
}

// ---------------- prep: fp32 -> fp16 conversion (weights) -------------------
__global__ void convf_kernel(const float* __restrict__ src,
                             __half* __restrict__ dst) {
    int i = blockIdx.x * blockDim.x + threadIdx.x;   // one float4 each
    float4 v = ((const float4*)src)[i];
    ((uint2*)dst)[i] = make_uint2(pack_h2(v.x, v.y), pack_h2(v.z, v.w));
}

// ---------------- grouped GEMM: fp16 single-pass, BK=32, NSTAGE=6,
//                  fragment double-buffered --------------------------------
// MODE 1: h = relu(scale * x @ w1 + b1) -> fp16 store
// MODE 2: out = h @ w2 + b2 -> fp32 scatter
template <int MODE>
__global__ __launch_bounds__(256, 1)
void moe_gemm_kernel(const __half* __restrict__ A16,
                     const __half* __restrict__ W16,
                     const float* __restrict__ bias,
                     float* __restrict__ out,
                     __half* __restrict__ oF,
                     int Ntot, int Ktot) {
    int e = blockIdx.z;
    int cnt = d_expCount[e];
    int mBase = blockIdx.y * BM;
    if (mBase >= cnt) return;
    int nBase = blockIdx.x * BN;

    extern __shared__ char smem[];
    uint32_t sb = smem_u32(smem);
    int tid = threadIdx.x;
    int wid = tid >> 5;
    int lane = tid & 31;

    // ---- loader assignment ----
    int r2 = tid >> 1;              // A row 0..127
    int hb = tid & 1;               // A 32B half of the 64B row-chunk
    bool aValid = (mBase + r2) < cnt;
    int aTok = aValid ? d_bucket[e * NTOK + mBase + r2] : d_bucket[e * NTOK];
    const __half* aP = A16 + (size_t)aTok * Ktot + hb * 16;
    uint32_t sAoff = r2 * AROWB + hb * 32;

    int rowB = tid >> 3;            // B k-row 0..31
    int segB = tid & 7;
    const __half* bP = W16 + (size_t)e * (size_t)Ktot * Ntot +
                       (size_t)rowB * Ntot + nBase;
    uint32_t sBoff = rowB * BROWB;

    auto load_stage = [&](int st, int k0) {
        uint32_t dst = sb + st * STAGE;
        cp16(dst + OFF_A + sAoff,      aP + k0);
        cp16(dst + OFF_A + sAoff + 16, aP + k0 + 8);
        size_t kk = (size_t)k0 * Ntot;
#pragma unroll
        for (int q = 0; q < 4; q++) {
            int s = segB + q * 8;   // 0..31 column chunks of 8 halfs
            cp16(dst + OFF_B + sBoff + s * 16, bP + kk + s * 8);
        }
    };

    // ---- compute assignment: 2 warpM x 4 warpN, warp tile 64x64 ----
    int warpM = wid >> 2;
    int warpN = wid & 3;
    int m0 = warpM * 64;
    int n0 = warpN * 64;

    float acc[32][4];
#pragma unroll
    for (int i = 0; i < 32; i++)
#pragma unroll
        for (int j = 0; j < 4; j++) acc[i][j] = 0.0f;

    int aRowL = m0 + (lane & 15);
    int aColB = (lane >> 4) * 16;
    int bKoff = (lane & 7) + ((lane >> 3) & 1) * 8;
    int bNoff = ((lane >> 4) & 1) * 8;

    // double-buffered fragments
    uint32_t af[2][4][4], bf[2][4][4];

    auto ldfrag = [&](int st, int s, int buf) {
        uint32_t base = sb + st * STAGE;
        uint32_t aAddr = base + OFF_A + aRowL * AROWB + aColB + s * 32;
#pragma unroll
        for (int mi = 0; mi < 4; mi++)
            ldm4(af[buf][mi], aAddr + mi * 16 * AROWB);
#pragma unroll
        for (int l = 0; l < 4; l++) {
            uint32_t bAddr = base + OFF_B + (s * 16 + bKoff) * BROWB +
                             (n0 + l * 16 + bNoff) * 2;
            ldm4t(bf[buf][l], bAddr);
        }
    };

    auto domma = [&](int buf) {
#pragma unroll
        for (int mi = 0; mi < 4; mi++)
#pragma unroll
            for (int l = 0; l < 4; l++) {
                mma16816(acc[mi * 8 + 2 * l],     af[buf][mi], bf[buf][l]);
                mma16816(acc[mi * 8 + 2 * l + 1], af[buf][mi], bf[buf][l] + 2);
            }
    };

    const int T = Ktot / BK;

    // prologue: fill NSTAGE-1 stages
#pragma unroll
    for (int i = 0; i < NSTAGE - 1; i++) {
        load_stage(i, i * BK);
        cp_commit();
    }

    for (int t = 0; t < T; t++) {
        cp_wait_deep();            // stage t resident
        __syncthreads();           // WAR protection on reused stage
        if (t + NSTAGE - 1 < T)
            load_stage((t + NSTAGE - 1) % NSTAGE, (t + NSTAGE - 1) * BK);
        cp_commit();               // always commit (empty near tail)

        int st = t % NSTAGE;
        ldfrag(st, 0, 0);          // exposed once per stage
        ldfrag(st, 1, 1);          // issued before MMAs; overlaps step-0 MMA
        domma(0);
        domma(1);
    }

    // ---- epilogue ----
#pragma unroll
    for (int mi = 0; mi < 4; mi++) {
#pragma unroll
        for (int half = 0; half < 2; half++) {
            int r = m0 + mi * 16 + half * 8 + (lane >> 2);
            int m = mBase + r;
            if (m >= cnt) continue;
            int token = d_bucket[e * NTOK + m];
            float sc = (MODE == 1) ? d_scale[token] : 1.0f;
#pragma unroll
            for (int nj = 0; nj < 8; nj++) {
                int col = nBase + n0 + nj * 8 + (lane & 3) * 2;
                float2 bv = *(const float2*)(bias + (size_t)e * Ntot + col);
                float v0 = acc[mi * 8 + nj][half * 2];
                float v1 = acc[mi * 8 + nj][half * 2 + 1];
                if (MODE == 1) {
                    v0 = fmaxf(v0 * sc + bv.x, 0.f);
                    v1 = fmaxf(v1 * sc + bv.y, 0.f);
                    *(uint32_t*)(oF + (size_t)token * Ntot + col) = pack_h2(v0, v1);
                } else {
                    float2 o;
                    o.x = v0 + bv.x;
                    o.y = v1 + bv.y;
                    *(float2*)(out + (size_t)token * Ntot + col) = o;
                }
            }
        }
    }
}

// ---------------- finalize ---------------------------------------------------
__global__ void finalize_kernel(float* __restrict__ out, int out_size) {
    int e = threadIdx.x;
    if (e >= 8) return;
    float s = 0.0f;
    for (int b = 0; b < 512; b++) s += d_psPartial[b * 8 + e];
    const int base = NTOK * DDIM;
    if (base + e < out_size)     out[base + e]     = (float)d_expCount[e];
    if (base + 8 + e < out_size) out[base + 8 + e] = s;
    if (e == 0 && base + 16 < out_size) out[base + 16] = 0.0f;
}

// ---------------- launch -----------------------------------------------------
extern "C" void kernel_launch(void* const* d_in, const int* in_sizes, int n_in,
                              void* d_out, int out_size) {
    const float* x   = (const float*)d_in[0];
    const float* wsw = (const float*)d_in[1];
    const float* bsw = (const float*)d_in[2];
    const float* w1  = (const float*)d_in[3];
    const float* b1  = (const float*)d_in[4];
    const float* w2  = (const float*)d_in[5];
    const float* b2  = (const float*)d_in[6];
    float* out = (float*)d_out;

    cudaFuncSetAttribute(moe_gemm_kernel<1>,
                         cudaFuncAttributeMaxDynamicSharedMemorySize, SMEM_TOTAL);
    cudaFuncSetAttribute(moe_gemm_kernel<2>,
                         cudaFuncAttributeMaxDynamicSharedMemorySize, SMEM_TOTAL);

    __half *x16, *w116, *w216, *h16;
    cudaGetSymbolAddress((void**)&x16, d_x16);
    cudaGetSymbolAddress((void**)&w116, d_w1_16);
    cudaGetSymbolAddress((void**)&w216, d_w2_16);
    cudaGetSymbolAddress((void**)&h16, d_h16);

    init_kernel<<<1, 32>>>();
    route_kernel<<<512, 256>>>(x, wsw, bsw, x16);       // also converts x
    convf_kernel<<<EEXP * DDIM * FDIM / 4 / 256, 256>>>(w1, w116);
    convf_kernel<<<EEXP * FDIM * DDIM / 4 / 256, 256>>>(w2, w216);

    moe_gemm_kernel<1><<<dim3(FDIM / BN, NTOK / BM, EEXP), 256, SMEM_TOTAL>>>(
        x16, w116, b1, nullptr, h16, FDIM, DDIM);
    moe_gemm_kernel<2><<<dim3(DDIM / BN, NTOK / BM, EEXP), 256, SMEM_TOTAL>>>(
        h16, w216, b2, out, nullptr, DDIM, FDIM);

    finalize_kernel<<<1, 8>>>(out, out_size);
}

// round 12
// speedup vs baseline: 1.1814x; 1.0006x over previous
#include <cuda_runtime.h>
#include <cuda_fp16.h>
#include <cstdint>

#define NTOK 4096
#define DDIM 1024
#define EEXP 8
#define FDIM 4096

#define BM 128
#define BN 256
#define BK 32
#define NSTAGE 6

// smem per stage: A 128 rows x 80B (64B data + 16B pad); B 32 rows x 528B
#define AROWB 80
#define BROWB 528
#define OFF_A  0
#define OFF_B  10240
#define STAGE  27136
#define SMEM_TOTAL (NSTAGE * STAGE)   // 162816

// ---------------- scratch ---------------------------------------------------
__device__ int    d_bucket[EEXP * NTOK];
__device__ int    d_expCount[EEXP];
__device__ float  d_scale[NTOK];
__device__ float  d_psPartial[512 * EEXP];
__device__ __half d_x16[(size_t)NTOK * DDIM];
__device__ __half d_w1_16[(size_t)EEXP * DDIM * FDIM];  // [E][K][N]
__device__ __half d_w2_16[(size_t)EEXP * FDIM * DDIM];  // [E][K][N]
__device__ __half d_h16[(size_t)NTOK * FDIM];

// ---------------- helpers ---------------------------------------------------
__device__ __forceinline__ uint32_t smem_u32(const void* p) {
    uint32_t a;
    asm("{ .reg .u64 t; cvta.to.shared.u64 t, %1; cvt.u32.u64 %0, t; }"
        : "=r"(a) : "l"(p));
    return a;
}
__device__ __forceinline__ void cp16(uint32_t s, const void* g) {
    asm volatile("cp.async.cg.shared.global [%0], [%1], 16;" :: "r"(s), "l"(g));
}
__device__ __forceinline__ void cp_commit() {
    asm volatile("cp.async.commit_group;" ::: "memory");
}
__device__ __forceinline__ void cp_wait_deep() {
    asm volatile("cp.async.wait_group %0;" :: "n"(NSTAGE - 2) : "memory");
}
__device__ __forceinline__ void ldm4(uint32_t* r, uint32_t a) {
    asm volatile("ldmatrix.sync.aligned.m8n8.x4.shared.b16 {%0,%1,%2,%3}, [%4];"
                 : "=r"(r[0]), "=r"(r[1]), "=r"(r[2]), "=r"(r[3]) : "r"(a));
}
__device__ __forceinline__ void ldm4t(uint32_t* r, uint32_t a) {
    asm volatile("ldmatrix.sync.aligned.m8n8.x4.trans.shared.b16 {%0,%1,%2,%3}, [%4];"
                 : "=r"(r[0]), "=r"(r[1]), "=r"(r[2]), "=r"(r[3]) : "r"(a));
}
__device__ __forceinline__ void mma16816(float* c, const uint32_t* a, const uint32_t* b) {
    asm volatile("mma.sync.aligned.m16n8k16.row.col.f32.f16.f16.f32 "
                 "{%0,%1,%2,%3}, {%4,%5,%6,%7}, {%8,%9}, {%0,%1,%2,%3};"
                 : "+f"(c[0]), "+f"(c[1]), "+f"(c[2]), "+f"(c[3])
                 : "r"(a[0]), "r"(a[1]), "r"(a[2]), "r"(a[3]),
                   "r"(b[0]), "r"(b[1]));
}
__device__ __forceinline__ uint32_t pack_h2(float a, float b) {
    __half2 h = __floats2half2_rn(a, b);
    return *reinterpret_cast<uint32_t*>(&h);
}

// ---------------- init ------------------------------------------------------
__global__ void init_kernel() {
    if (threadIdx.x < EEXP) d_expCount[threadIdx.x] = 0;
}

// ---------------- routing (1 warp / token, fp64 acc) + x fp16 conversion ----
__global__ void route_kernel(const float* __restrict__ x,
                             const float* __restrict__ wsw,
                             const float* __restrict__ bsw,
                             __half* __restrict__ x16) {
    // fused: convert this block's share of x to fp16 (8 float4 per thread)
    {
        int base = (blockIdx.x * blockDim.x + threadIdx.x) * 8;
#pragma unroll
        for (int i = 0; i < 8; i++) {
            float4 v = ((const float4*)x)[base + i];
            ((uint2*)x16)[base + i] =
                make_uint2(pack_h2(v.x, v.y), pack_h2(v.z, v.w));
        }
    }

    int warp = threadIdx.x >> 5;
    int lane = threadIdx.x & 31;
    int token = blockIdx.x * 8 + warp;

    const float* xr = x + (size_t)token * DDIM;
    double acc[8];
#pragma unroll
    for (int e = 0; e < 8; e++) acc[e] = 0.0;

    for (int i = lane; i < DDIM; i += 32) {
        float xv = xr[i];
        float4 wa = *(const float4*)(wsw + (size_t)i * 8);
        float4 wb = *(const float4*)(wsw + (size_t)i * 8 + 4);
        acc[0] += (double)xv * wa.x;
        acc[1] += (double)xv * wa.y;
        acc[2] += (double)xv * wa.z;
        acc[3] += (double)xv * wa.w;
        acc[4] += (double)xv * wb.x;
        acc[5] += (double)xv * wb.y;
        acc[6] += (double)xv * wb.z;
        acc[7] += (double)xv * wb.w;
    }
#pragma unroll
    for (int e = 0; e < 8; e++) {
#pragma unroll
        for (int off = 16; off > 0; off >>= 1)
            acc[e] += __shfl_down_sync(0xffffffffu, acc[e], off);
    }

    __shared__ float probs[8][8];
    if (lane == 0) {
        float l[8];
#pragma unroll
        for (int e = 0; e < 8; e++) l[e] = (float)acc[e] + bsw[e];
        int am = 0;
        float mx = l[0];
#pragma unroll
        for (int e = 1; e < 8; e++)
            if (l[e] > mx) { mx = l[e]; am = e; }
        float p[8], sum = 0.0f;
#pragma unroll
        for (int e = 0; e < 8; e++) { p[e] = expf(l[e] - mx); sum += p[e]; }
        float inv = 1.0f / sum;
#pragma unroll
        for (int e = 0; e < 8; e++) probs[warp][e] = p[e] * inv;

        d_scale[token] = inv;
        int pos = atomicAdd(&d_expCount[am], 1);
        d_bucket[am * NTOK + pos] = token;
    }
    __syncthreads();
    if (threadIdx.x < 8) {
        float s = 0.0f;
#pragma unroll
        for (int w = 0; w < 8; w++) s += probs[w][threadIdx.x];
        d_psPartial[blockIdx.x * 8 + threadIdx.x] = s;
    }
}

// ---------------- prep: fp32 -> fp16 conversion (weights) -------------------
__global__ void convf_kernel(const float* __restrict__ src,
                             __half* __restrict__ dst) {
    int i = blockIdx.x * blockDim.x + threadIdx.x;   // one float4 each
    float4 v = ((const float4*)src)[i];
    ((uint2*)dst)[i] = make_uint2(pack_h2(v.x, v.y), pack_h2(v.z, v.w));
}

// ---------------- grouped GEMM: fp16 single-pass, BK=32, NSTAGE=6,
//                  fragment double-buffered --------------------------------
// MODE 1: h = relu(scale * x @ w1 + b1) -> fp16 store
// MODE 2: out = h @ w2 + b2 -> fp32 scatter
template <int MODE>
__global__ __launch_bounds__(256, 1)
void moe_gemm_kernel(const __half* __restrict__ A16,
                     const __half* __restrict__ W16,
                     const float* __restrict__ bias,
                     float* __restrict__ out,
                     __half* __restrict__ oF,
                     int Ntot, int Ktot) {
    int e = blockIdx.z;
    int cnt = d_expCount[e];
    int mBase = blockIdx.y * BM;
    if (mBase >= cnt) return;
    int nBase = blockIdx.x * BN;

    extern __shared__ char smem[];
    uint32_t sb = smem_u32(smem);
    int tid = threadIdx.x;
    int wid = tid >> 5;
    int lane = tid & 31;

    // ---- loader assignment ----
    int r2 = tid >> 1;              // A row 0..127
    int hb = tid & 1;               // A 32B half of the 64B row-chunk
    bool aValid = (mBase + r2) < cnt;
    int aTok = aValid ? d_bucket[e * NTOK + mBase + r2] : d_bucket[e * NTOK];
    const __half* aP = A16 + (size_t)aTok * Ktot + hb * 16;
    uint32_t sAoff = r2 * AROWB + hb * 32;

    int rowB = tid >> 3;            // B k-row 0..31
    int segB = tid & 7;
    const __half* bP = W16 + (size_t)e * (size_t)Ktot * Ntot +
                       (size_t)rowB * Ntot + nBase;
    uint32_t sBoff = rowB * BROWB;

    auto load_stage = [&](int st, int k0) {
        uint32_t dst = sb + st * STAGE;
        cp16(dst + OFF_A + sAoff,      aP + k0);
        cp16(dst + OFF_A + sAoff + 16, aP + k0 + 8);
        size_t kk = (size_t)k0 * Ntot;
#pragma unroll
        for (int q = 0; q < 4; q++) {
            int s = segB + q * 8;   // 0..31 column chunks of 8 halfs
            cp16(dst + OFF_B + sBoff + s * 16, bP + kk + s * 8);
        }
    };

    // ---- compute assignment: 2 warpM x 4 warpN, warp tile 64x64 ----
    int warpM = wid >> 2;
    int warpN = wid & 3;
    int m0 = warpM * 64;
    int n0 = warpN * 64;

    float acc[32][4];
#pragma unroll
    for (int i = 0; i < 32; i++)
#pragma unroll
        for (int j = 0; j < 4; j++) acc[i][j] = 0.0f;

    int aRowL = m0 + (lane & 15);
    int aColB = (lane >> 4) * 16;
    int bKoff = (lane & 7) + ((lane >> 3) & 1) * 8;
    int bNoff = ((lane >> 4) & 1) * 8;

    // double-buffered fragments
    uint32_t af[2][4][4], bf[2][4][4];

    auto ldfrag = [&](int st, int s, int buf) {
        uint32_t base = sb + st * STAGE;
        uint32_t aAddr = base + OFF_A + aRowL * AROWB + aColB + s * 32;
#pragma unroll
        for (int mi = 0; mi < 4; mi++)
            ldm4(af[buf][mi], aAddr + mi * 16 * AROWB);
#pragma unroll
        for (int l = 0; l < 4; l++) {
            uint32_t bAddr = base + OFF_B + (s * 16 + bKoff) * BROWB +
                             (n0 + l * 16 + bNoff) * 2;
            ldm4t(bf[buf][l], bAddr);
        }
    };

    auto domma = [&](int buf) {
#pragma unroll
        for (int mi = 0; mi < 4; mi++)
#pragma unroll
            for (int l = 0; l < 4; l++) {
                mma16816(acc[mi * 8 + 2 * l],     af[buf][mi], bf[buf][l]);
                mma16816(acc[mi * 8 + 2 * l + 1], af[buf][mi], bf[buf][l] + 2);
            }
    };

    const int T = Ktot / BK;

    // prologue: fill NSTAGE-1 stages
#pragma unroll
    for (int i = 0; i < NSTAGE - 1; i++) {
        load_stage(i, i * BK);
        cp_commit();
    }

    for (int t = 0; t < T; t++) {
        cp_wait_deep();            // stage t resident
        __syncthreads();           // WAR protection on reused stage
        if (t + NSTAGE - 1 < T)
            load_stage((t + NSTAGE - 1) % NSTAGE, (t + NSTAGE - 1) * BK);
        cp_commit();               // always commit (empty near tail)

        int st = t % NSTAGE;
        ldfrag(st, 0, 0);          // exposed once per stage
        ldfrag(st, 1, 1);          // issued before MMAs; overlaps step-0 MMA
        domma(0);
        domma(1);
    }

    // ---- epilogue ----
#pragma unroll
    for (int mi = 0; mi < 4; mi++) {
#pragma unroll
        for (int half = 0; half < 2; half++) {
            int r = m0 + mi * 16 + half * 8 + (lane >> 2);
            int m = mBase + r;
            if (m >= cnt) continue;
            int token = d_bucket[e * NTOK + m];
            float sc = (MODE == 1) ? d_scale[token] : 1.0f;
#pragma unroll
            for (int nj = 0; nj < 8; nj++) {
                int col = nBase + n0 + nj * 8 + (lane & 3) * 2;
                float2 bv = *(const float2*)(bias + (size_t)e * Ntot + col);
                float v0 = acc[mi * 8 + nj][half * 2];
                float v1 = acc[mi * 8 + nj][half * 2 + 1];
                if (MODE == 1) {
                    v0 = fmaxf(v0 * sc + bv.x, 0.f);
                    v1 = fmaxf(v1 * sc + bv.y, 0.f);
                    *(uint32_t*)(oF + (size_t)token * Ntot + col) = pack_h2(v0, v1);
                } else {
                    float2 o;
                    o.x = v0 + bv.x;
                    o.y = v1 + bv.y;
                    *(float2*)(out + (size_t)token * Ntot + col) = o;
                }
            }
        }
    }
}

// ---------------- finalize ---------------------------------------------------
__global__ void finalize_kernel(float* __restrict__ out, int out_size) {
    int e = threadIdx.x;
    if (e >= 8) return;
    float s = 0.0f;
    for (int b = 0; b < 512; b++) s += d_psPartial[b * 8 + e];
    const int base = NTOK * DDIM;
    if (base + e < out_size)     out[base + e]     = (float)d_expCount[e];
    if (base + 8 + e < out_size) out[base + 8 + e] = s;
    if (e == 0 && base + 16 < out_size) out[base + 16] = 0.0f;
}

// ---------------- launch -----------------------------------------------------
extern "C" void kernel_launch(void* const* d_in, const int* in_sizes, int n_in,
                              void* d_out, int out_size) {
    const float* x   = (const float*)d_in[0];
    const float* wsw = (const float*)d_in[1];
    const float* bsw = (const float*)d_in[2];
    const float* w1  = (const float*)d_in[3];
    const float* b1  = (const float*)d_in[4];
    const float* w2  = (const float*)d_in[5];
    const float* b2  = (const float*)d_in[6];
    float* out = (float*)d_out;

    cudaFuncSetAttribute(moe_gemm_kernel<1>,
                         cudaFuncAttributeMaxDynamicSharedMemorySize, SMEM_TOTAL);
    cudaFuncSetAttribute(moe_gemm_kernel<2>,
                         cudaFuncAttributeMaxDynamicSharedMemorySize, SMEM_TOTAL);

    __half *x16, *w116, *w216, *h16;
    cudaGetSymbolAddress((void**)&x16, d_x16);
    cudaGetSymbolAddress((void**)&w116, d_w1_16);
    cudaGetSymbolAddress((void**)&w216, d_w2_16);
    cudaGetSymbolAddress((void**)&h16, d_h16);

    init_kernel<<<1, 32>>>();
    route_kernel<<<512, 256>>>(x, wsw, bsw, x16);       // also converts x
    convf_kernel<<<EEXP * DDIM * FDIM / 4 / 256, 256>>>(w1, w116);
    convf_kernel<<<EEXP * FDIM * DDIM / 4 / 256, 256>>>(w2, w216);

    moe_gemm_kernel<1><<<dim3(FDIM / BN, NTOK / BM, EEXP), 256, SMEM_TOTAL>>>(
        x16, w116, b1, nullptr, h16, FDIM, DDIM);
    moe_gemm_kernel<2><<<dim3(DDIM / BN, NTOK / BM, EEXP), 256, SMEM_TOTAL>>>(
        h16, w216, b2, out, nullptr, DDIM, FDIM);

    finalize_kernel<<<1, 8>>>(out, out_size);
}